// round 2
// baseline (speedup 1.0000x reference)
#include <cuda_runtime.h>

#define D    128
#define NMAX 50000
#define EMAX 800000

// ---------------- scratch (device globals: allocation-free) ----------------
__device__ __align__(16) float g_A[(size_t)NMAX * D];   // h_lin / h
__device__ __align__(16) float g_B[(size_t)NMAX * D];   // agg1 / hm
__device__ __align__(16) float g_Wcat[D * D];           // [w_mu | w_ls]
__device__ float g_deg[NMAX];
__device__ float g_dis[NMAX];
__device__ __align__(16) float g_norm[EMAX];
__device__ int   g_src[EMAX];
__device__ int   g_dst[EMAX];
__device__ int   g_is32;                                // 1 if edge_index is int32

// ---------------- edge-index dtype detection ----------------
// If the buffer is int32 (2E values in [0,n)), reading it as int64 combines
// two int32 words; the high word is nonzero for ~all pairs -> value >= n.
// If it is genuine int64, every value is in [0,n). One block, ~1024 samples.
__global__ void k_detect(const long long* __restrict__ ei, int total64, int n) {
    __shared__ int bad;
    if (threadIdx.x == 0) bad = 0;
    __syncthreads();
    int lim = total64 < 1024 ? total64 : 1024;
    for (int i = threadIdx.x; i < lim; i += blockDim.x) {
        long long v = ei[i];
        if (v < 0 || v >= (long long)n) bad = 1;
    }
    __syncthreads();
    if (threadIdx.x == 0) g_is32 = bad;
}

// ---------------- small utility kernels ----------------
__global__ void k_prep(const void* __restrict__ ei, int E, int n) {
    int i = blockIdx.x * blockDim.x + threadIdx.x;
    if (i < E) {
        int s, d;
        if (g_is32) {
            const int* e32 = (const int*)ei;
            s = e32[i];
            d = e32[E + i];
        } else {
            const long long* e64 = (const long long*)ei;
            s = (int)e64[i];
            d = (int)e64[(size_t)E + i];
        }
        g_src[i] = s;
        g_dst[i] = d;
    }
    if (i < n) g_deg[i] = 0.0f;
}

__global__ void k_deg(int E) {
    int e = blockIdx.x * blockDim.x + threadIdx.x;
    if (e < E) atomicAdd(&g_deg[g_dst[e]], 1.0f);
}

__global__ void k_dis(int n) {
    int i = blockIdx.x * blockDim.x + threadIdx.x;
    if (i < n) {
        float d = g_deg[i];
        g_dis[i] = (d > 0.0f) ? rsqrtf(d) : 0.0f;
    }
}

__global__ void k_norm(int E) {
    int e = blockIdx.x * blockDim.x + threadIdx.x;
    if (e < E) g_norm[e] = g_dis[g_src[e]] * g_dis[g_dst[e]];
}

__global__ void k_cat(const float* __restrict__ wmu, const float* __restrict__ wls) {
    int i = blockIdx.x * blockDim.x + threadIdx.x;
    if (i < D * D) {
        int k = i >> 7, c = i & 127;
        g_Wcat[i] = (c < 64) ? wmu[k * 64 + c] : wls[k * 64 + (c - 64)];
    }
}

__global__ void k_zero(float4* __restrict__ p, int n4) {
    int i = blockIdx.x * blockDim.x + threadIdx.x;
    if (i < n4) p[i] = make_float4(0.f, 0.f, 0.f, 0.f);
}

// ---------------- dense GEMM: OUT[n,128] = X[n,128] @ W[128,128] ----------------
// Block: 256 threads, tile 64 rows x 128 cols, thread tile 8 rows x 4 cols.
__global__ void k_gemm(const float* __restrict__ X, const float* __restrict__ W,
                       float* __restrict__ OUT, int nrows) {
    __shared__ float Ws[32][128];
    __shared__ float Xs[32][65];   // +1 pad: conflict-free transposed writes

    int tx = threadIdx.x;
    int cg = tx & 31;    // column group: cols [4*cg, 4*cg+3]
    int rg = tx >> 5;    // row group: rows [8*rg, 8*rg+7]
    int rowBase = blockIdx.x * 64;

    float acc[8][4];
#pragma unroll
    for (int i = 0; i < 8; i++)
#pragma unroll
        for (int j = 0; j < 4; j++) acc[i][j] = 0.0f;

    for (int kk = 0; kk < 128; kk += 32) {
        // W slab: rows [kk, kk+31] are contiguous 4096 floats
        const float4* wg = (const float4*)(W + (size_t)kk * 128);
        float4* ws4 = (float4*)&Ws[0][0];
#pragma unroll
        for (int i = 0; i < 4; i++) ws4[tx + i * 256] = wg[tx + i * 256];

        // X slab, transposed: Xs[k][row]
        int kx = tx & 31, r0 = tx >> 5;
#pragma unroll
        for (int i = 0; i < 8; i++) {
            int row  = r0 + i * 8;
            int grow = rowBase + row;
            Xs[kx][row] = (grow < nrows) ? X[(size_t)grow * 128 + kk + kx] : 0.0f;
        }
        __syncthreads();

#pragma unroll 8
        for (int k = 0; k < 32; k++) {
            float4 w = ((const float4*)&Ws[k][0])[cg];
#pragma unroll
            for (int i = 0; i < 8; i++) {
                float xv = Xs[k][rg * 8 + i];
                acc[i][0] += xv * w.x;
                acc[i][1] += xv * w.y;
                acc[i][2] += xv * w.z;
                acc[i][3] += xv * w.w;
            }
        }
        __syncthreads();
    }

#pragma unroll
    for (int i = 0; i < 8; i++) {
        int grow = rowBase + rg * 8 + i;
        if (grow < nrows)
            ((float4*)(OUT + (size_t)grow * 128))[cg] =
                make_float4(acc[i][0], acc[i][1], acc[i][2], acc[i][3]);
    }
}

// ---------------- edge scatter: one warp per edge ----------------
__device__ __forceinline__ void red4(float* p, float4 v) {
    asm volatile("red.global.add.v4.f32 [%0], {%1, %2, %3, %4};"
                 :: "l"(p), "f"(v.x), "f"(v.y), "f"(v.z), "f"(v.w)
                 : "memory");
}

__global__ void k_scatter(const float* __restrict__ h, float* __restrict__ out, int E) {
    int t = blockIdx.x * blockDim.x + threadIdx.x;
    int e = t >> 5, lane = t & 31;
    if (e >= E) return;
    int s = g_src[e], d = g_dst[e];
    float nm = g_norm[e];
    float4 v = ((const float4*)(h + (size_t)s * 128))[lane];
    v.x *= nm; v.y *= nm; v.z *= nm; v.w *= nm;
    red4(out + (size_t)d * 128 + lane * 4, v);
}

// Layer 2: scatter hm[src]*norm straight into d_out (mu half / logstd half).
__global__ void k_scatter_out(const float* __restrict__ h, float* __restrict__ out,
                              int half, int E) {
    int t = blockIdx.x * blockDim.x + threadIdx.x;
    int e = t >> 5, lane = t & 31;
    if (e >= E) return;
    int s = g_src[e], d = g_dst[e];
    float nm = g_norm[e];
    float4 v = ((const float4*)(h + (size_t)s * 128))[lane];
    v.x *= nm; v.y *= nm; v.z *= nm; v.w *= nm;
    int col = lane * 4;
    float* p = (col < 64) ? (out + (size_t)d * 64 + col)
                          : (out + half + (size_t)d * 64 + (col - 64));
    red4(p, v);
}

// h = relu(agg1 + b1), written A <- f(B)
__global__ void k_bias_relu(const float* __restrict__ b1, int n) {
    int i = blockIdx.x * blockDim.x + threadIdx.x;   // over n*32 float4s
    if (i < n * 32) {
        float4 v = ((const float4*)g_B)[i];
        float4 b = ((const float4*)b1)[i & 31];
        float4 r;
        r.x = fmaxf(v.x + b.x, 0.0f);
        r.y = fmaxf(v.y + b.y, 0.0f);
        r.z = fmaxf(v.z + b.z, 0.0f);
        r.w = fmaxf(v.w + b.w, 0.0f);
        ((float4*)g_A)[i] = r;
    }
}

// out[mu half] += b_mu ; out[logstd half] += b_ls
__global__ void k_bias_out(float* __restrict__ out, const float* __restrict__ bmu,
                           const float* __restrict__ bls, int half4) {
    int i = blockIdx.x * blockDim.x + threadIdx.x;
    if (i < half4) {
        float4 bm = ((const float4*)bmu)[i & 15];
        float4 bl = ((const float4*)bls)[i & 15];
        float4 a = ((float4*)out)[i];
        a.x += bm.x; a.y += bm.y; a.z += bm.z; a.w += bm.w;
        ((float4*)out)[i] = a;
        float4 c = ((float4*)out)[i + half4];
        c.x += bl.x; c.y += bl.y; c.z += bl.z; c.w += bl.w;
        ((float4*)out)[i + half4] = c;
    }
}

// ---------------- launch ----------------
extern "C" void kernel_launch(void* const* d_in, const int* in_sizes, int n_in,
                              void* d_out, int out_size) {
    const float* x   = (const float*)d_in[0];
    const void*  ei  = d_in[1];
    const float* w1  = (const float*)d_in[2];
    const float* b1  = (const float*)d_in[3];
    const float* wmu = (const float*)d_in[4];
    const float* bmu = (const float*)d_in[5];
    const float* wls = (const float*)d_in[6];
    const float* bls = (const float*)d_in[7];
    float* out = (float*)d_out;

    int n = in_sizes[0] / D;          // 50000
    int E = in_sizes[1] / 2;          // 800000
    int half = out_size / 2;          // n*64

    float *A, *B, *Wc;
    cudaGetSymbolAddress((void**)&A,  g_A);
    cudaGetSymbolAddress((void**)&B,  g_B);
    cudaGetSymbolAddress((void**)&Wc, g_Wcat);

    const int T = 256;
    int mEn = (E > n) ? E : n;

    // dtype probe: safe to read min(2E, 1024) int64 words only if the buffer is
    // at least that big in bytes; 2E int32 = E int64 words >= 1024 here.
    k_detect<<<1, 256>>>((const long long*)ei, E, n);
    k_prep<<<(mEn + T - 1) / T, T>>>(ei, E, n);
    k_deg<<<(E + T - 1) / T, T>>>(E);
    k_dis<<<(n + T - 1) / T, T>>>(n);
    k_norm<<<(E + T - 1) / T, T>>>(E);
    k_cat<<<(D * D + T - 1) / T, T>>>(wmu, wls);

    // layer 1: h_lin = x @ w1
    k_gemm<<<(n + 63) / 64, T>>>(x, w1, A, n);
    // agg1 = 0 ; agg1[dst] += h_lin[src]*norm
    k_zero<<<((n * 32) + T - 1) / T, T>>>((float4*)B, n * 32);
    k_scatter<<<((E * 32) + T - 1) / T, T>>>(A, B, E);
    // h = relu(agg1 + b1)
    k_bias_relu<<<((n * 32) + T - 1) / T, T>>>(b1, n);

    // layer 2 (fused mu|logstd): hm = h @ [w_mu|w_ls]
    k_gemm<<<(n + 63) / 64, T>>>(A, Wc, B, n);
    // d_out = 0 ; scatter into split halves ; add biases
    k_zero<<<((out_size / 4) + T - 1) / T, T>>>((float4*)out, out_size / 4);
    k_scatter_out<<<((E * 32) + T - 1) / T, T>>>(B, out, half, E);
    k_bias_out<<<((half / 4) + T - 1) / T, T>>>(out, bmu, bls, half / 4);
}